// round 8
// baseline (speedup 1.0000x reference)
#include <cuda_runtime.h>
#include <cstdint>

// YOLOv1 loss: preds [N,7,7,30] f32, labels [N,7,7,30] f32 -> scalar f32.
// Warp-synchronous persistent CTAs (1 warp each), 4-stage cp.async pipeline,
// zero barriers in the hot loop. HBM-bound streaming reduction.

#define TILE_CELLS 32
#define THREADS 32
#define FLOATS_PER_CELL 30
#define F4_PER_ARRAY 240            // 32*30/4
#define F4_PER_TILE 480             // preds + labels
#define ITERS_PER_LANE 15           // 480 / 32 lanes
#define STAGES 4
#define MAX_BLOCKS 1036             // 7 CTAs/SM * 148 SMs

__global__ void zero_out_kernel(float* out) { out[0] = 0.0f; }

__device__ __forceinline__ uint32_t smem_addr_u32(const void* p) {
    return (uint32_t)__cvta_generic_to_shared(p);
}

#define CP_ASYNC16(dst_u32, src_ptr) \
    asm volatile("cp.async.cg.shared.global [%0], [%1], 16;\n" :: "r"(dst_u32), "l"(src_ptr))
#define CP_COMMIT() asm volatile("cp.async.commit_group;\n" ::)
#define CP_WAIT3()  asm volatile("cp.async.wait_group 3;\n" ::)

__device__ __forceinline__ float iou_cxcywh(const float* a, const float* b) {
    float ax1 = a[0] - a[2] * 0.5f, ay1 = a[1] - a[3] * 0.5f;
    float ax2 = a[0] + a[2] * 0.5f, ay2 = a[1] + a[3] * 0.5f;
    float bx1 = b[0] - b[2] * 0.5f, by1 = b[1] - b[3] * 0.5f;
    float bx2 = b[0] + b[2] * 0.5f, by2 = b[1] + b[3] * 0.5f;
    float iw = fmaxf(fminf(ax2, bx2) - fmaxf(ax1, bx1), 0.0f);
    float ih = fmaxf(fminf(ay2, by2) - fmaxf(ay1, by1), 0.0f);
    float inter = iw * ih;
    float uni = a[2] * a[3] + b[2] * b[3] - inter;
    return inter / (uni + 1e-10f);
}

__global__ __launch_bounds__(THREADS) void yolo_loss_wspipe_kernel(
    const float4* __restrict__ preds4,
    const float4* __restrict__ labels4,
    float* __restrict__ out,
    int n_tiles, float inv_batch)
{
    // [stage][ preds(240) | labels(240) ]
    __shared__ float4 buf[STAGES][F4_PER_TILE];

    const int lane = threadIdx.x;

    // Issue one tile into stage s. Always commits a group (empty when t OOR)
    // so wait_group counting stays exact. Tiling is exact: no tail predicates.
    auto issue_tile = [&](int t, int s) {
        if (t < n_tiles) {
            const int base4 = t * F4_PER_ARRAY;
#pragma unroll
            for (int k = 0; k < ITERS_PER_LANE; ++k) {
                const int i = lane + 32 * k;               // 0..479
                const float4* src = (i < F4_PER_ARRAY)
                    ? (preds4  + base4 + i)
                    : (labels4 + base4 + (i - F4_PER_ARRAY));
                CP_ASYNC16(smem_addr_u32(&buf[s][i]), src);
            }
        }
        CP_COMMIT();
    };

    float loss = 0.0f;
    const int g = gridDim.x;
    const int t0 = blockIdx.x;

    // Prologue: 3 tiles already in flight before the loop.
    issue_tile(t0,         0);
    issue_tile(t0 + g,     1);
    issue_tile(t0 + 2 * g, 2);

    int s = 0;
    for (int t = t0; t < n_tiles; t += g) {
        issue_tile(t + 3 * g, (s + 3) & 3);   // keep 4 groups in flight
        CP_WAIT3();                            // oldest (stage s) landed
        __syncwarp();

        {
            const float* bp = (const float*)buf[s];
            const float* p = bp + lane * FLOATS_PER_CELL;
            const float* l = bp + 4 * F4_PER_ARRAY + lane * FLOATS_PER_CELL;

            const float obj = (l[4] == 1.0f) ? 1.0f : 0.0f;

            const float i1 = iou_cxcywh(p, l);
            const float i2 = iou_cxcywh(p + 5, l);
            const bool b1 = i1 > i2;

            const float* pr = b1 ? p : (p + 5);
            const float* po = b1 ? (p + 5) : p;
            const float* lr = b1 ? l : (l + 5);   // label box duplicated in data
            const float iou_r = b1 ? i1 : i2;
            const float iou_o = b1 ? i2 : i1;

            float dx = pr[0] - lr[0];
            float dy = pr[1] - lr[1];
            float d_xy = dx * dx + dy * dy;

            float sw = sqrtf(pr[2]) - sqrtf(lr[2]);
            float sh = sqrtf(pr[3]) - sqrtf(lr[3]);
            float d_wh = sw * sw + sh * sh;

            float d_obj = pr[4] - iou_r;  d_obj *= d_obj;
            float d_no  = po[4] - iou_o;  d_no  *= d_no;
            float d_out = p[4] * p[4] + p[9] * p[9];

            float d_cls = 0.0f;
#pragma unroll
            for (int c = 10; c < 30; ++c) {
                float d = p[c] - l[c];
                d_cls = fmaf(d, d, d_cls);
            }

            loss += obj * (5.0f * d_xy + d_wh + d_obj + 0.5f * d_no + d_cls)
                  + (1.0f - obj) * 0.5f * d_out;
        }

        s = (s + 1) & 3;
    }

    // Warp reduce + one atomic per CTA.
#pragma unroll
    for (int o = 16; o > 0; o >>= 1)
        loss += __shfl_xor_sync(0xffffffffu, loss, o);
    if (lane == 0)
        atomicAdd(out, loss * inv_batch);
}

extern "C" void kernel_launch(void* const* d_in, const int* in_sizes, int n_in,
                              void* d_out, int out_size)
{
    const float4* preds4  = (const float4*)d_in[0];
    const float4* labels4 = (const float4*)d_in[1];
    float* out = (float*)d_out;

    const int total_floats = in_sizes[0];                    // N*7*7*30
    const int n_cells = total_floats / FLOATS_PER_CELL;      // N*49
    const int batch = n_cells / 49;                          // N
    const int n_tiles = n_cells / TILE_CELLS;                // exact: 802816/32 = 25088

    zero_out_kernel<<<1, 1>>>(out);

    const int n_blocks = (n_tiles < MAX_BLOCKS) ? n_tiles : MAX_BLOCKS;
    yolo_loss_wspipe_kernel<<<n_blocks, THREADS>>>(preds4, labels4, out,
                                                   n_tiles, 1.0f / (float)batch);
}

// round 10
// speedup vs baseline: 1.0571x; 1.0571x over previous
#include <cuda_runtime.h>
#include <cstdint>

// YOLOv1 loss: preds [N,7,7,30] f32, labels [N,7,7,30] f32 -> scalar f32.
// Persistent CTAs, 3-stage cp.async pipeline, ONE barrier per tile,
// single kernel (last-block final reduction). HBM-bound streaming reduction.

#define TILE_CELLS 64
#define THREADS 96
#define FLOATS_PER_CELL 30
#define F4_PER_ARRAY 480            // 64*30/4
#define F4_PER_TILE 960             // preds + labels
#define ITERS 10                    // 960 / 96 threads
#define STAGES 3
#define MAX_BLOCKS 592              // 4 CTAs/SM * 148 SMs

__device__ float g_partials[MAX_BLOCKS];
__device__ unsigned int g_count;    // zero-init; atomicInc wraps back to 0 -> replay-safe

__device__ __forceinline__ uint32_t smem_addr_u32(const void* p) {
    return (uint32_t)__cvta_generic_to_shared(p);
}

#define CP_ASYNC16(dst_u32, src_ptr) \
    asm volatile("cp.async.cg.shared.global [%0], [%1], 16;\n" :: "r"(dst_u32), "l"(src_ptr))
#define CP_COMMIT() asm volatile("cp.async.commit_group;\n" ::)
#define CP_WAIT1()  asm volatile("cp.async.wait_group 1;\n" ::)

__device__ __forceinline__ float iou_cxcywh(const float* a, const float* b) {
    float ax1 = a[0] - a[2] * 0.5f, ay1 = a[1] - a[3] * 0.5f;
    float ax2 = a[0] + a[2] * 0.5f, ay2 = a[1] + a[3] * 0.5f;
    float bx1 = b[0] - b[2] * 0.5f, by1 = b[1] - b[3] * 0.5f;
    float bx2 = b[0] + b[2] * 0.5f, by2 = b[1] + b[3] * 0.5f;
    float iw = fmaxf(fminf(ax2, bx2) - fmaxf(ax1, bx1), 0.0f);
    float ih = fmaxf(fminf(ay2, by2) - fmaxf(ay1, by1), 0.0f);
    float inter = iw * ih;
    float uni = a[2] * a[3] + b[2] * b[3] - inter;
    return inter / (uni + 1e-10f);
}

__global__ __launch_bounds__(THREADS) void yolo_loss_3s_kernel(
    const float4* __restrict__ preds4,
    const float4* __restrict__ labels4,
    float* __restrict__ out,
    int n_tiles, float inv_batch)
{
    __shared__ float4 buf[STAGES][F4_PER_TILE];   // [stage][preds(480)|labels(480)]
    __shared__ float warp_s[THREADS / 32];
    __shared__ bool is_last;

    const int tid = threadIdx.x;
    const int g = gridDim.x;

    // Issue one tile into stage s; always commits (possibly empty) group so
    // wait_group counting stays exact. Tiling is exact (802816 % 64 == 0).
    auto issue_tile = [&](int t, int s) {
        if (t < n_tiles) {
            const int base4 = t * F4_PER_ARRAY;
#pragma unroll
            for (int k = 0; k < ITERS; ++k) {
                const int i = tid + THREADS * k;           // 0..959
                const float4* src = (i < F4_PER_ARRAY)
                    ? (preds4  + base4 + i)
                    : (labels4 + base4 + (i - F4_PER_ARRAY));
                CP_ASYNC16(smem_addr_u32(&buf[s][i]), src);
            }
        }
        CP_COMMIT();
    };

    float loss = 0.0f;
    const int t0 = blockIdx.x;

    // Prologue: two tiles in flight.
    issue_tile(t0,     0);
    issue_tile(t0 + g, 1);

    int s = 0;
    for (int t = t0; t < n_tiles; t += g) {
        CP_WAIT1();          // stage s landed (s+1 still in flight)
        __syncthreads();     // everyone finished stage s-1 (== s+2) last iter
        issue_tile(t + 2 * g, (s + 2 >= STAGES) ? s - 1 : s + 2);  // refill s+2 mod 3

        if (tid < TILE_CELLS) {
            const float* bp = (const float*)buf[s];
            const float* p = bp + tid * FLOATS_PER_CELL;
            const float* l = bp + 4 * F4_PER_ARRAY + tid * FLOATS_PER_CELL;

            const float obj = (l[4] == 1.0f) ? 1.0f : 0.0f;

            const float i1 = iou_cxcywh(p, l);
            const float i2 = iou_cxcywh(p + 5, l);
            const bool b1 = i1 > i2;

            const float* pr = b1 ? p : (p + 5);
            const float* po = b1 ? (p + 5) : p;
            const float* lr = b1 ? l : (l + 5);   // label box duplicated in data
            const float iou_r = b1 ? i1 : i2;
            const float iou_o = b1 ? i2 : i1;

            float dx = pr[0] - lr[0];
            float dy = pr[1] - lr[1];
            float d_xy = dx * dx + dy * dy;

            float sw = sqrtf(pr[2]) - sqrtf(lr[2]);
            float sh = sqrtf(pr[3]) - sqrtf(lr[3]);
            float d_wh = sw * sw + sh * sh;

            float d_obj = pr[4] - iou_r;  d_obj *= d_obj;
            float d_no  = po[4] - iou_o;  d_no  *= d_no;
            float d_out = p[4] * p[4] + p[9] * p[9];

            float d_cls = 0.0f;
#pragma unroll
            for (int c = 10; c < 30; ++c) {
                float d = p[c] - l[c];
                d_cls = fmaf(d, d, d_cls);
            }

            loss += obj * (5.0f * d_xy + d_wh + d_obj + 0.5f * d_no + d_cls)
                  + (1.0f - obj) * 0.5f * d_out;
        }

        s = (s + 1 >= STAGES) ? 0 : s + 1;
    }

    // Per-block reduction -> partials slot.
#pragma unroll
    for (int o = 16; o > 0; o >>= 1)
        loss += __shfl_xor_sync(0xffffffffu, loss, o);
    if ((tid & 31) == 0) warp_s[tid >> 5] = loss;
    __syncthreads();

    if (tid == 0) {
        float bsum = warp_s[0] + warp_s[1] + warp_s[2];
        g_partials[blockIdx.x] = bsum;
        __threadfence();
        unsigned int v = atomicInc(&g_count, gridDim.x - 1); // wraps to 0 on last
        is_last = (v == gridDim.x - 1);
    }
    __syncthreads();

    // Last-arriving block folds all partials and writes the scalar output.
    if (is_last) {
        float t = 0.0f;
        for (int i = tid; i < (int)gridDim.x; i += THREADS)
            t += g_partials[i];
#pragma unroll
        for (int o = 16; o > 0; o >>= 1)
            t += __shfl_xor_sync(0xffffffffu, t, o);
        if ((tid & 31) == 0) warp_s[tid >> 5] = t;
        __syncthreads();
        if (tid == 0)
            out[0] = (warp_s[0] + warp_s[1] + warp_s[2]) * inv_batch;
    }
}

extern "C" void kernel_launch(void* const* d_in, const int* in_sizes, int n_in,
                              void* d_out, int out_size)
{
    const float4* preds4  = (const float4*)d_in[0];
    const float4* labels4 = (const float4*)d_in[1];
    float* out = (float*)d_out;

    const int total_floats = in_sizes[0];                    // N*7*7*30
    const int n_cells = total_floats / FLOATS_PER_CELL;      // N*49
    const int batch = n_cells / 49;                          // N
    const int n_tiles = n_cells / TILE_CELLS;                // exact: 802816/64 = 12544

    const int n_blocks = (n_tiles < MAX_BLOCKS) ? n_tiles : MAX_BLOCKS;
    yolo_loss_3s_kernel<<<n_blocks, THREADS>>>(preds4, labels4, out,
                                               n_tiles, 1.0f / (float)batch);
}